// round 1
// baseline (speedup 1.0000x reference)
#include <cuda_runtime.h>

#define NN 50000
#define EE 800000
#define ETOT (EE + NN)
#define DD 128
#define NBSCAN ((NN + 1023) / 1024)

// ---------------- static device scratch (no allocations allowed) ----------------
__device__ float g_h[NN * DD];     // node features between layers
__device__ float g_xl[NN * DD];    // lin_l output
__device__ float g_xr[NN * DD];    // lin_r output
__device__ int   g_deg[NN];
__device__ int   g_offs[NN + 1];
__device__ int   g_cur[NN];
__device__ int   g_srcs[ETOT];
__device__ int   g_bsums[NBSCAN];

// ---------------- CSR build ----------------
__global__ void zero_counts() {
    int i = blockIdx.x * blockDim.x + threadIdx.x;
    if (i < NN) { g_deg[i] = 0; g_cur[i] = 0; }
}

__global__ void count_edges(const int* __restrict__ ei) {
    int t = blockIdx.x * blockDim.x + threadIdx.x;
    if (t < ETOT) {
        int dst = (t < EE) ? ei[EE + t] : (t - EE);   // row 1 of [2,E] = dst; tail = self loops
        atomicAdd(&g_deg[dst], 1);
    }
}

// block-local inclusive scan: 1024 elems / block (256 thr x 4)
__global__ void scan_block() {
    __shared__ int sm[256];
    int t = threadIdx.x;
    int base = blockIdx.x * 1024 + t * 4;
    int v0 = (base + 0 < NN) ? g_deg[base + 0] : 0;
    int v1 = (base + 1 < NN) ? g_deg[base + 1] : 0;
    int v2 = (base + 2 < NN) ? g_deg[base + 2] : 0;
    int v3 = (base + 3 < NN) ? g_deg[base + 3] : 0;
    v1 += v0; v2 += v1; v3 += v2;
    sm[t] = v3;
    __syncthreads();
    #pragma unroll
    for (int off = 1; off < 256; off <<= 1) {
        int add = (t >= off) ? sm[t - off] : 0;
        __syncthreads();
        sm[t] += add;
        __syncthreads();
    }
    int prev = (t > 0) ? sm[t - 1] : 0;
    if (base + 0 < NN) g_offs[base + 0] = prev + v0;  // inclusive (local)
    if (base + 1 < NN) g_offs[base + 1] = prev + v1;
    if (base + 2 < NN) g_offs[base + 2] = prev + v2;
    if (base + 3 < NN) g_offs[base + 3] = prev + v3;
    if (t == 255) g_bsums[blockIdx.x] = sm[255];
}

__global__ void scan_spine() {
    if (threadIdx.x == 0) {
        int acc = 0;
        for (int i = 0; i < NBSCAN; i++) { int v = g_bsums[i]; g_bsums[i] = acc; acc += v; }
    }
}

__global__ void scan_fix() {
    int i = blockIdx.x * blockDim.x + threadIdx.x;
    if (i < NN) g_offs[i] = g_offs[i] - g_deg[i] + g_bsums[i >> 10];  // exclusive global
    if (i == 0) g_offs[NN] = ETOT;
}

__global__ void fill_edges(const int* __restrict__ ei) {
    int t = blockIdx.x * blockDim.x + threadIdx.x;
    if (t < ETOT) {
        int src, dst;
        if (t < EE) { src = ei[t]; dst = ei[EE + t]; }
        else        { src = t - EE; dst = src; }
        int pos = g_offs[dst] + atomicAdd(&g_cur[dst], 1);
        g_srcs[pos] = src;
    }
}

// ---------------- layer 0 GEMM: [N,7] x [7,128] x2, trivial K ----------------
__global__ void gemm0(const float* __restrict__ x,
                      const float* __restrict__ Wl0, const float* __restrict__ Wr0,
                      const float* __restrict__ bl0, const float* __restrict__ br0) {
    int node = blockIdx.x;
    int j = threadIdx.x;                 // 0..255
    __shared__ float xs[7];
    if (j < 7) xs[j] = x[node * 7 + j];
    __syncthreads();
    const float* W = (j < 128) ? Wl0 : Wr0;
    int c = j & 127;
    float acc = (j < 128) ? bl0[c] : br0[c];
    #pragma unroll
    for (int k = 0; k < 7; k++) acc += xs[k] * W[k * 128 + c];
    if (j < 128) g_xl[node * DD + c] = acc;
    else         g_xr[node * DD + c] = acc;
}

// ---------------- mid-layer GEMM: relu(h)[N,128] x W[128,256] (+bias) ----------------
// C tile: 64 rows x 256 cols, 256 threads, 8x8 micro tile. K staged by 32.
__global__ __launch_bounds__(256, 2) void gemm_mid(const float* __restrict__ Wl_,
                                                   const float* __restrict__ Wr_,
                                                   const float* __restrict__ bl_,
                                                   const float* __restrict__ br_) {
    __shared__ float As[32][65];        // [k][row], padded
    __shared__ float Bs[32][256];       // [k][col]
    int tid = threadIdx.x;
    int tx = tid & 31;                  // col group: cols tx*8 .. tx*8+7
    int ty = tid >> 5;                  // row group: rows ty*8 .. ty*8+7
    int row0 = blockIdx.x * 64;

    float acc[8][8];
    #pragma unroll
    for (int i = 0; i < 8; i++)
        #pragma unroll
        for (int j = 0; j < 8; j++) acc[i][j] = 0.f;

    for (int k0 = 0; k0 < 128; k0 += 32) {
        // A tile: 64x32, relu fused
        #pragma unroll
        for (int q = 0; q < 8; q++) {
            int l = tid + q * 256;
            int r = l >> 5, k = l & 31;
            int row = row0 + r;
            float v = (row < NN) ? g_h[row * DD + k0 + k] : 0.f;
            As[k][r] = fmaxf(v, 0.f);
        }
        // B tile: 32x256 (Wl | Wr)
        #pragma unroll
        for (int q = 0; q < 32; q++) {
            int l = tid + q * 256;
            int k = l >> 8, c = l & 255;
            float w = (c < 128) ? Wl_[(k0 + k) * 128 + c]
                                : Wr_[(k0 + k) * 128 + (c - 128)];
            Bs[k][c] = w;
        }
        __syncthreads();
        #pragma unroll
        for (int k = 0; k < 32; k++) {
            float a_[8], b_[8];
            #pragma unroll
            for (int i = 0; i < 8; i++) a_[i] = As[k][ty * 8 + i];
            float4 b01 = *(float4*)&Bs[k][tx * 8];
            float4 b23 = *(float4*)&Bs[k][tx * 8 + 4];
            b_[0] = b01.x; b_[1] = b01.y; b_[2] = b01.z; b_[3] = b01.w;
            b_[4] = b23.x; b_[5] = b23.y; b_[6] = b23.z; b_[7] = b23.w;
            #pragma unroll
            for (int i = 0; i < 8; i++)
                #pragma unroll
                for (int j = 0; j < 8; j++) acc[i][j] += a_[i] * b_[j];
        }
        __syncthreads();
    }

    int c0 = tx * 8;
    float bias_[8];
    #pragma unroll
    for (int j = 0; j < 8; j++)
        bias_[j] = (c0 < 128) ? bl_[c0 + j] : br_[c0 - 128 + j];

    #pragma unroll
    for (int i = 0; i < 8; i++) {
        int row = row0 + ty * 8 + i;
        if (row < NN) {
            float4 o0 = make_float4(acc[i][0] + bias_[0], acc[i][1] + bias_[1],
                                    acc[i][2] + bias_[2], acc[i][3] + bias_[3]);
            float4 o1 = make_float4(acc[i][4] + bias_[4], acc[i][5] + bias_[5],
                                    acc[i][6] + bias_[6], acc[i][7] + bias_[7]);
            if (c0 < 128) {
                *(float4*)&g_xl[row * DD + c0]     = o0;
                *(float4*)&g_xl[row * DD + c0 + 4] = o1;
            } else {
                *(float4*)&g_xr[row * DD + c0 - 128]     = o0;
                *(float4*)&g_xr[row * DD + c0 - 128 + 4] = o1;
            }
        }
    }
}

// ---------------- attention + aggregation: warp per destination node, online softmax ----------------
__global__ void attn(const float* __restrict__ avec, const float* __restrict__ bvec,
                     float* __restrict__ outp) {
    const unsigned FULL = 0xffffffffu;
    int w = (blockIdx.x * blockDim.x + threadIdx.x) >> 5;
    if (w >= NN) return;
    int lane = threadIdx.x & 31;

    float4 xr4 = *(float4*)&g_xr[w * DD + lane * 4];
    float4 a4  = *(const float4*)&avec[lane * 4];

    int p = g_offs[w], end = g_offs[w + 1];   // deg >= 1 (self loop)
    float m = -1e30f, s = 0.f;
    float ax = 0.f, ay = 0.f, az = 0.f, aw = 0.f;

    int src = g_srcs[p];
    float4 xl4 = *(float4*)&g_xl[src * DD + lane * 4];

    while (p < end) {
        float4 cur = xl4;
        int pn = p + 1;
        if (pn < end) {
            int s2 = g_srcs[pn];
            xl4 = *(float4*)&g_xl[s2 * DD + lane * 4];
        }
        float vx = cur.x + xr4.x; vx = (vx > 0.f) ? vx : 0.2f * vx;
        float vy = cur.y + xr4.y; vy = (vy > 0.f) ? vy : 0.2f * vy;
        float vz = cur.z + xr4.z; vz = (vz > 0.f) ? vz : 0.2f * vz;
        float vw = cur.w + xr4.w; vw = (vw > 0.f) ? vw : 0.2f * vw;
        float d = vx * a4.x + vy * a4.y + vz * a4.z + vw * a4.w;
        d += __shfl_xor_sync(FULL, d, 16);
        d += __shfl_xor_sync(FULL, d, 8);
        d += __shfl_xor_sync(FULL, d, 4);
        d += __shfl_xor_sync(FULL, d, 2);
        d += __shfl_xor_sync(FULL, d, 1);

        float mn  = fmaxf(m, d);
        float sc  = __expf(m - mn);   // exp(-inf)=0 on first edge
        float wgt = __expf(d - mn);
        s  = s * sc + wgt;
        ax = ax * sc + wgt * cur.x;
        ay = ay * sc + wgt * cur.y;
        az = az * sc + wgt * cur.z;
        aw = aw * sc + wgt * cur.w;
        m = mn;
        p = pn;
    }

    float inv = 1.f / s;
    float4 b4 = *(const float4*)&bvec[lane * 4];
    float* o = outp ? outp : g_h;
    float4 r = make_float4(ax * inv + b4.x, ay * inv + b4.y,
                           az * inv + b4.z, aw * inv + b4.w);
    *(float4*)&o[w * DD + lane * 4] = r;
}

// ---------------- launch ----------------
extern "C" void kernel_launch(void* const* d_in, const int* in_sizes, int n_in,
                              void* d_out, int out_size) {
    const float* x    = (const float*)d_in[0];
    const int*   ei   = (const int*)d_in[1];
    const float* Wl0  = (const float*)d_in[2];
    const float* Wr0  = (const float*)d_in[3];
    const float* bl0  = (const float*)d_in[4];
    const float* br0  = (const float*)d_in[5];
    const float* Wl   = (const float*)d_in[6];
    const float* Wr   = (const float*)d_in[7];
    const float* bl   = (const float*)d_in[8];
    const float* br   = (const float*)d_in[9];
    const float* att  = (const float*)d_in[10];
    const float* bias = (const float*)d_in[11];
    float* out = (float*)d_out;

    // CSR build (per launch, graph-captured)
    zero_counts<<<(NN + 255) / 256, 256>>>();
    count_edges<<<(ETOT + 255) / 256, 256>>>(ei);
    scan_block<<<NBSCAN, 256>>>();
    scan_spine<<<1, 32>>>();
    scan_fix<<<(NN + 255) / 256, 256>>>();
    fill_edges<<<(ETOT + 255) / 256, 256>>>(ei);

    const int attn_blocks = (NN * 32 + 255) / 256;
    const int gemm_blocks = (NN + 63) / 64;

    // layer 0
    gemm0<<<NN, 256>>>(x, Wl0, Wr0, bl0, br0);
    attn<<<attn_blocks, 256>>>(att, bias, nullptr);

    // layers 1..4 (relu fused into gemm A-load)
    for (int t = 1; t < 5; t++) {
        gemm_mid<<<gemm_blocks, 256>>>(Wl + (size_t)(t - 1) * 128 * 128,
                                       Wr + (size_t)(t - 1) * 128 * 128,
                                       bl + (size_t)(t - 1) * 128,
                                       br + (size_t)(t - 1) * 128);
        attn<<<attn_blocks, 256>>>(att + (size_t)t * 128, bias + (size_t)t * 128,
                                   (t == 4) ? out : nullptr);
    }
}